// round 5
// baseline (speedup 1.0000x reference)
#include <cuda_runtime.h>
#include <cuda_bf16.h>
#include <cstdint>

// WaveletPreprocessing: level-1 orthonormal Haar wavedec2 + waverec2 is an
// exact identity (perfect reconstruction, even dims, crop is a no-op) ->
// the task is a pure 512 MiB HBM->HBM copy.
//
// R3 -> R4: the SM/LSU copy path appears pinned at ~84% of DRAM peak
// (R2 = 164.4us best; persistent-grid R3 regressed). Try the copy-engine
// path: a single cudaMemcpyAsync D2D node in the captured graph. CEs have
// deeper, better-scheduled DRAM request queues than the LSU path and on
// recent archs beat SM copy kernels (~88-92% of peak). Explicitly allowed
// by the harness rules ("cudaMemcpyAsync device-to-device ... are fine").
//
// Fallback SM kernel (R2 config) kept below, compiled but only used for a
// non-multiple-of-16-bytes remainder (never taken for this shape).

constexpr int UNROLL  = 8;
constexpr int THREADS = 512;

__global__ void __launch_bounds__(THREADS, 4)
haar_identity_copy_kernel(const float4* __restrict__ src,
                          float4* __restrict__ dst,
                          long long n_vec)
{
    long long base = (long long)blockIdx.x * (THREADS * UNROLL) + threadIdx.x;

    if (base + (long long)(UNROLL - 1) * THREADS < n_vec) {
        float4 v[UNROLL];
#pragma unroll
        for (int k = 0; k < UNROLL; k++)
            v[k] = __ldcs(&src[base + (long long)k * THREADS]);
#pragma unroll
        for (int k = 0; k < UNROLL; k++)
            __stcs(&dst[base + (long long)k * THREADS], v[k]);
    } else {
#pragma unroll
        for (int k = 0; k < UNROLL; k++) {
            long long idx = base + (long long)k * THREADS;
            if (idx < n_vec) __stcs(&dst[idx], __ldcs(&src[idx]));
        }
    }
}

extern "C" void kernel_launch(void* const* d_in, const int* in_sizes, int n_in,
                              void* d_out, int out_size)
{
    const float* x = (const float*)d_in[0];
    float* out = (float*)d_out;

    long long n = (long long)in_sizes[0];       // 134,217,728 floats
    size_t bytes = (size_t)n * sizeof(float);   // 512 MiB

    // Copy-engine path: single async D2D memcpy node on the capture
    // (legacy default) stream.
    cudaMemcpyAsync(out, x, bytes, cudaMemcpyDeviceToDevice, 0);

    (void)n_in; (void)out_size;
}

// round 6
// speedup vs baseline: 2.0492x; 2.0492x over previous
#include <cuda_runtime.h>
#include <cuda_bf16.h>
#include <cstdint>

// WaveletPreprocessing: level-1 orthonormal Haar wavedec2 + waverec2 is an
// exact identity (perfect reconstruction, even dims, crop is a no-op) ->
// the task is a pure 512 MiB HBM->HBM copy.
//
// History: R2 (one-shot grid, __ldcs/__stcs, UNROLL=8) = 164.4us, DRAM 84.3%.
//          R3 persistent grid regressed (lost cross-CTA load/store overlap).
//          R4 copy-engine memcpy regressed 2x (CE ~3.1 TB/s « LSU 6.7 TB/s).
// R5: R2 structure, stores __stcs -> __stwt (write-through). On a pure
// streaming copy no store is re-read; write-through sends stores straight to
// the DRAM scheduler instead of accumulating dirty L2 victims whose
// writebacks contend with demand read fills.

constexpr int UNROLL  = 8;
constexpr int THREADS = 512;

__global__ void __launch_bounds__(THREADS, 4)
haar_identity_copy_kernel(const float4* __restrict__ src,
                          float4* __restrict__ dst,
                          long long n_vec)
{
    // One 64 KiB tile (THREADS*UNROLL float4) per block; one-shot grid.
    long long base = (long long)blockIdx.x * (THREADS * UNROLL) + threadIdx.x;

    if (base + (long long)(UNROLL - 1) * THREADS < n_vec) {
        // 8 independent coalesced evict-first LDG.128 front-batched,
        // then 8 write-through STG.128.
        float4 v[UNROLL];
#pragma unroll
        for (int k = 0; k < UNROLL; k++)
            v[k] = __ldcs(&src[base + (long long)k * THREADS]);
#pragma unroll
        for (int k = 0; k < UNROLL; k++)
            __stwt(&dst[base + (long long)k * THREADS], v[k]);
    } else {
        // Tail tile (never taken for n_vec = 2^25, kept for shape-safety).
#pragma unroll
        for (int k = 0; k < UNROLL; k++) {
            long long idx = base + (long long)k * THREADS;
            if (idx < n_vec) __stwt(&dst[idx], __ldcs(&src[idx]));
        }
    }
}

extern "C" void kernel_launch(void* const* d_in, const int* in_sizes, int n_in,
                              void* d_out, int out_size)
{
    const float* x = (const float*)d_in[0];
    float* out = (float*)d_out;

    long long n = (long long)in_sizes[0];   // 134,217,728 floats
    long long n_vec = n / 4;                // 33,554,432 float4 (exact)

    long long tile = (long long)THREADS * UNROLL;   // 4096 float4 / block
    int blocks = (int)((n_vec + tile - 1) / tile);  // 8192 blocks

    haar_identity_copy_kernel<<<blocks, THREADS>>>(
        (const float4*)x, (float4*)out, n_vec);

    (void)n_in; (void)out_size;
}

// round 7
// speedup vs baseline: 2.0894x; 1.0196x over previous
#include <cuda_runtime.h>
#include <cuda_bf16.h>
#include <cstdint>

// WaveletPreprocessing: level-1 orthonormal Haar wavedec2 + waverec2 is an
// exact identity (perfect reconstruction, even dims, crop is a no-op) ->
// the task is a pure 512 MiB HBM->HBM copy (information-theoretic optimum:
// output bytes == input bytes).
//
// Search history:
//   R1 plain float4 grid-stride:        178.9us (DRAM 74.2%)
//   R2 __ldcs/__stcs, 8x float4/thread: 164.4us (DRAM 84.3%, 6.68 TB/s)  <- best
//   R3 persistent grid:                 181.0us (lost cross-CTA overlap)
//   R4 copy-engine memcpyAsync:         344.2us (CE ~3.1 TB/s)
//   R5 __stwt write-through stores:     168.0us (loses LTS victim bursting)
// R6: revert to R2 verbatim. 83.5% of spec is the measured turnaround-bound
// copy wall on this part; LTS cap is path-independent (TMA == LDG), so no
// mechanism with predicted upside remains.

constexpr int UNROLL  = 8;
constexpr int THREADS = 512;

__global__ void __launch_bounds__(THREADS, 4)
haar_identity_copy_kernel(const float4* __restrict__ src,
                          float4* __restrict__ dst,
                          long long n_vec)
{
    // One 64 KiB tile (THREADS*UNROLL float4) per block; one-shot grid.
    // Fresh blocks' front-batched loads overlap retiring blocks' store
    // drains across tile boundaries (this is what the persistent grid lost).
    long long base = (long long)blockIdx.x * (THREADS * UNROLL) + threadIdx.x;

    if (base + (long long)(UNROLL - 1) * THREADS < n_vec) {
        // 8 independent coalesced evict-first LDG.128 front-batched,
        // then 8 evict-first STG.128.
        float4 v[UNROLL];
#pragma unroll
        for (int k = 0; k < UNROLL; k++)
            v[k] = __ldcs(&src[base + (long long)k * THREADS]);
#pragma unroll
        for (int k = 0; k < UNROLL; k++)
            __stcs(&dst[base + (long long)k * THREADS], v[k]);
    } else {
        // Tail tile (never taken for n_vec = 2^25, kept for shape-safety).
#pragma unroll
        for (int k = 0; k < UNROLL; k++) {
            long long idx = base + (long long)k * THREADS;
            if (idx < n_vec) __stcs(&dst[idx], __ldcs(&src[idx]));
        }
    }
}

extern "C" void kernel_launch(void* const* d_in, const int* in_sizes, int n_in,
                              void* d_out, int out_size)
{
    const float* x = (const float*)d_in[0];
    float* out = (float*)d_out;

    long long n = (long long)in_sizes[0];   // 134,217,728 floats
    long long n_vec = n / 4;                // 33,554,432 float4 (exact)

    long long tile = (long long)THREADS * UNROLL;   // 4096 float4 / block
    int blocks = (int)((n_vec + tile - 1) / tile);  // 8192 blocks

    haar_identity_copy_kernel<<<blocks, THREADS>>>(
        (const float4*)x, (float4*)out, n_vec);

    (void)n_in; (void)out_size;
}

// round 8
// speedup vs baseline: 2.2046x; 1.0551x over previous
#include <cuda_runtime.h>
#include <cuda_bf16.h>
#include <cstdint>

// WaveletPreprocessing: level-1 orthonormal Haar wavedec2 + waverec2 is an
// exact identity -> pure 512 MiB HBM->HBM copy.
//
// Search history:
//   R1 plain float4 grid-stride:        178.9us (DRAM 74.2%)
//   R2 __ldcs/__stcs, 512T x 8 float4:  164.4us (DRAM 84.3%)  <- best, reproduced R6
//   R3 persistent grid:                 181.0us
//   R4 copy-engine memcpyAsync:         344.2us
//   R5 __stwt stores:                   168.0us
// R7: probe true per-warp MLP depth. regs=32 showed ptxas pipelined the
// 8-deep buffer into ~2-3 live float4. 256T x 16 float4 (same 64 KiB tile,
// same 8192-block grid) forces ~16 genuinely outstanding LDG.128 per thread
// (near per-warp M_max~55 for the warp) before the store phase, trading
// occupancy for scoreboard depth.

constexpr int UNROLL  = 16;
constexpr int THREADS = 256;

__global__ void __launch_bounds__(THREADS, 2)
haar_identity_copy_kernel(const float4* __restrict__ src,
                          float4* __restrict__ dst,
                          long long n_vec)
{
    // One 64 KiB tile (THREADS*UNROLL float4) per block; one-shot grid.
    long long base = (long long)blockIdx.x * (THREADS * UNROLL) + threadIdx.x;

    if (base + (long long)(UNROLL - 1) * THREADS < n_vec) {
        // 16 independent coalesced evict-first LDG.128 front-batched,
        // then 16 evict-first STG.128.
        float4 v[UNROLL];
#pragma unroll
        for (int k = 0; k < UNROLL; k++)
            v[k] = __ldcs(&src[base + (long long)k * THREADS]);
#pragma unroll
        for (int k = 0; k < UNROLL; k++)
            __stcs(&dst[base + (long long)k * THREADS], v[k]);
    } else {
        // Tail tile (never taken for n_vec = 2^25, kept for shape-safety).
#pragma unroll
        for (int k = 0; k < UNROLL; k++) {
            long long idx = base + (long long)k * THREADS;
            if (idx < n_vec) __stcs(&dst[idx], __ldcs(&src[idx]));
        }
    }
}

extern "C" void kernel_launch(void* const* d_in, const int* in_sizes, int n_in,
                              void* d_out, int out_size)
{
    const float* x = (const float*)d_in[0];
    float* out = (float*)d_out;

    long long n = (long long)in_sizes[0];   // 134,217,728 floats
    long long n_vec = n / 4;                // 33,554,432 float4 (exact)

    long long tile = (long long)THREADS * UNROLL;   // 4096 float4 / block
    int blocks = (int)((n_vec + tile - 1) / tile);  // 8192 blocks

    haar_identity_copy_kernel<<<blocks, THREADS>>>(
        (const float4*)x, (float4*)out, n_vec);

    (void)n_in; (void)out_size;
}

// round 9
// speedup vs baseline: 2.2059x; 1.0006x over previous
#include <cuda_runtime.h>
#include <cuda_bf16.h>
#include <cstdint>

// WaveletPreprocessing: level-1 orthonormal Haar wavedec2 + waverec2 is an
// exact identity -> pure 512 MiB HBM->HBM copy.
//
// Search history:
//   R1 plain float4 grid-stride:         178.9us (DRAM 74.2%)
//   R2 __ldcs/__stcs, 512T x  8 float4:  164.4us (DRAM 84.3%)
//   R3 persistent grid:                  181.0us
//   R4 copy-engine memcpyAsync:          344.2us
//   R5 __stwt stores:                    168.0us
//   R7 256T x 16 float4 (regs=72):       156.1us (DRAM 85.7%)  <- best
// R8: keep scaling the winning axis (true per-warp MLP depth):
// 128T x 32 float4 per thread (same 64 KiB tile, 8192-block one-shot grid).
// 32 outstanding LDG.128/warp is still under the measured per-warp
// M_max ~ 55; ~160 regs/thread, no spill. Occupancy ~19% is acceptable --
// R7 proved per-warp scoreboard depth, not occupancy, is the limiter.

constexpr int UNROLL  = 32;
constexpr int THREADS = 128;

__global__ void __launch_bounds__(THREADS, 2)
haar_identity_copy_kernel(const float4* __restrict__ src,
                          float4* __restrict__ dst,
                          long long n_vec)
{
    // One 64 KiB tile (THREADS*UNROLL float4) per block; one-shot grid.
    long long base = (long long)blockIdx.x * (THREADS * UNROLL) + threadIdx.x;

    if (base + (long long)(UNROLL - 1) * THREADS < n_vec) {
        // 32 independent coalesced evict-first LDG.128 front-batched,
        // then 32 evict-first STG.128.
        float4 v[UNROLL];
#pragma unroll
        for (int k = 0; k < UNROLL; k++)
            v[k] = __ldcs(&src[base + (long long)k * THREADS]);
#pragma unroll
        for (int k = 0; k < UNROLL; k++)
            __stcs(&dst[base + (long long)k * THREADS], v[k]);
    } else {
        // Tail tile (never taken for n_vec = 2^25, kept for shape-safety).
#pragma unroll
        for (int k = 0; k < UNROLL; k++) {
            long long idx = base + (long long)k * THREADS;
            if (idx < n_vec) __stcs(&dst[idx], __ldcs(&src[idx]));
        }
    }
}

extern "C" void kernel_launch(void* const* d_in, const int* in_sizes, int n_in,
                              void* d_out, int out_size)
{
    const float* x = (const float*)d_in[0];
    float* out = (float*)d_out;

    long long n = (long long)in_sizes[0];   // 134,217,728 floats
    long long n_vec = n / 4;                // 33,554,432 float4 (exact)

    long long tile = (long long)THREADS * UNROLL;   // 4096 float4 / block
    int blocks = (int)((n_vec + tile - 1) / tile);  // 8192 blocks

    haar_identity_copy_kernel<<<blocks, THREADS>>>(
        (const float4*)x, (float4*)out, n_vec);

    (void)n_in; (void)out_size;
}